// round 5
// baseline (speedup 1.0000x reference)
#include <cuda_runtime.h>
#include <cstdint>
#include <cstddef>

// ---------------------------------------------------------------------------
// Problem constants (shapes fixed by the dataset)
// ---------------------------------------------------------------------------
#define NMAX 50000
#define EMAX 400000
#define FD   256      // feature width at every layer (IN = H*HID = H*OUT = 256)
#define HH   4        // heads
#define NEG_SLOPE 0.2f

// ---------------------------------------------------------------------------
// Scratch (device globals — no runtime allocation allowed)
// ---------------------------------------------------------------------------
__device__ __align__(128) float        g_feat [NMAX * FD];
__device__ __align__(128) float        g_bufA [NMAX * FD];
__device__ __align__(128) float        g_bufB [NMAX * FD];
__device__ __align__(128) float        g_agg  [NMAX * FD];
__device__ __align__(128) float        g_el   [NMAX * HH];
__device__ __align__(128) float        g_er   [NMAX * HH];
__device__ __align__(128) unsigned int g_emax [NMAX * HH];
__device__ __align__(128) float        g_denom[NMAX * HH];
__device__ __align__(128) float        g_ex   [EMAX * HH];

// ---------------------------------------------------------------------------
// Packed f32x2 helpers (Blackwell dual-rate fp32 FMA)
// ---------------------------------------------------------------------------
__device__ __forceinline__ unsigned long long pack2(float x, float y) {
    unsigned long long r;
    asm("mov.b64 %0, {%1, %2};" : "=l"(r) : "f"(x), "f"(y));
    return r;
}
__device__ __forceinline__ void fma2(unsigned long long& d,
                                     unsigned long long a,
                                     unsigned long long b) {
    asm("fma.rn.f32x2 %0, %1, %2, %0;" : "+l"(d) : "l"(a), "l"(b));
}
__device__ __forceinline__ float2 unpack2(unsigned long long v) {
    float2 f;
    asm("mov.b64 {%0, %1}, %2;" : "=f"(f.x), "=f"(f.y) : "l"(v));
    return f;
}

// Order-preserving float <-> uint key for atomicMax-based segment max
__device__ __forceinline__ unsigned int fkey(float f) {
    unsigned int u = __float_as_uint(f);
    return (u & 0x80000000u) ? ~u : (u | 0x80000000u);
}
__device__ __forceinline__ float fkey_dec(unsigned int k) {
    return __uint_as_float((k & 0x80000000u) ? (k & 0x7fffffffu) : ~k);
}

// ---------------------------------------------------------------------------
// SGEMM: C(n x 256) = A(n x 256) * B(256 x 256), fp32, f32x2 accumulators.
// BM=BN=128, BK=16, 256 threads, 8x8 outputs/thread (split 4+4 cols at +64).
// ---------------------------------------------------------------------------
__global__ __launch_bounds__(256, 2)
void sgemm_kernel(const float* __restrict__ A, const float* __restrict__ B,
                  int nrows)
{
    __shared__ float As[16][128];   // As[k][row] (transposed)
    __shared__ float Bs[16][128];   // Bs[k][col]

    const int tid  = threadIdx.x;
    const int brow = blockIdx.x * 128;
    const int bcol = blockIdx.y * 128;
    const int tx   = tid & 15;
    const int ty   = tid >> 4;
    const int row0 = ty * 8;
    const int colA = tx * 4;        // cols colA..colA+3 and colA+64..colA+67

    unsigned long long acc[8][4];
#pragma unroll
    for (int i = 0; i < 8; i++)
#pragma unroll
        for (int j = 0; j < 4; j++) acc[i][j] = 0ULL;

    const int fa = tid * 2;

    for (int kt = 0; kt < 256; kt += 16) {
        // ---- A tile: 128x16, stored transposed into As ----
#pragma unroll
        for (int q = 0; q < 2; q++) {
            int f  = fa + q;
            int r  = f >> 2;
            int k0 = (f & 3) * 4;
            float4 v = make_float4(0.f, 0.f, 0.f, 0.f);
            int grow = brow + r;
            if (grow < nrows)
                v = *(const float4*)(A + (size_t)grow * 256 + kt + k0);
            As[k0 + 0][r] = v.x;
            As[k0 + 1][r] = v.y;
            As[k0 + 2][r] = v.z;
            As[k0 + 3][r] = v.w;
        }
        // ---- B tile: 16x128 ----
#pragma unroll
        for (int q = 0; q < 2; q++) {
            int f = fa + q;
            int k = f >> 5;
            int c = (f & 31) * 4;
            float4 v = *(const float4*)(B + (size_t)(kt + k) * 256 + bcol + c);
            *(float4*)&Bs[k][c] = v;
        }
        __syncthreads();

#pragma unroll
        for (int k = 0; k < 16; k++) {
            float4 a0 = *(const float4*)&As[k][row0];
            float4 a1 = *(const float4*)&As[k][row0 + 4];
            unsigned long long b0 = *(const unsigned long long*)&Bs[k][colA];
            unsigned long long b1 = *(const unsigned long long*)&Bs[k][colA + 2];
            unsigned long long b2 = *(const unsigned long long*)&Bs[k][colA + 64];
            unsigned long long b3 = *(const unsigned long long*)&Bs[k][colA + 66];
            float av[8] = {a0.x, a0.y, a0.z, a0.w, a1.x, a1.y, a1.z, a1.w};
#pragma unroll
            for (int i = 0; i < 8; i++) {
                unsigned long long aa = pack2(av[i], av[i]);
                fma2(acc[i][0], aa, b0);
                fma2(acc[i][1], aa, b1);
                fma2(acc[i][2], aa, b2);
                fma2(acc[i][3], aa, b3);
            }
        }
        __syncthreads();
    }

    // ---- store to g_feat ----
#pragma unroll
    for (int i = 0; i < 8; i++) {
        int grow = brow + row0 + i;
        if (grow >= nrows) break;
        float2 c0 = unpack2(acc[i][0]);
        float2 c1 = unpack2(acc[i][1]);
        float2 c2 = unpack2(acc[i][2]);
        float2 c3 = unpack2(acc[i][3]);
        float* C = g_feat + (size_t)grow * 256 + bcol;
        *(float4*)(C + colA)      = make_float4(c0.x, c0.y, c1.x, c1.y);
        *(float4*)(C + colA + 64) = make_float4(c2.x, c2.y, c3.x, c3.y);
    }
}

// ---------------------------------------------------------------------------
// Per-node attention projections: el[n,h] = <feat[n,h,:], al[h,:]>, same er.
// One warp per node.
// ---------------------------------------------------------------------------
__global__ void attn_prep_kernel(const float* __restrict__ al,
                                 const float* __restrict__ ar, int n)
{
    int gt   = blockIdx.x * blockDim.x + threadIdx.x;
    int node = gt >> 5;
    int lane = gt & 31;
    if (node >= n) return;

    const float4* f4 = (const float4*)(g_feat + (size_t)node * 256);
    float4 f0 = f4[lane * 2];
    float4 f1 = f4[lane * 2 + 1];

    int head = lane >> 3;
    int off  = head * 64 + (lane & 7) * 8;
    float4 l0 = *(const float4*)(al + off);
    float4 l1 = *(const float4*)(al + off + 4);
    float4 r0 = *(const float4*)(ar + off);
    float4 r1 = *(const float4*)(ar + off + 4);

    float pel = f0.x * l0.x + f0.y * l0.y + f0.z * l0.z + f0.w * l0.w +
                f1.x * l1.x + f1.y * l1.y + f1.z * l1.z + f1.w * l1.w;
    float per = f0.x * r0.x + f0.y * r0.y + f0.z * r0.z + f0.w * r0.w +
                f1.x * r1.x + f1.y * r1.y + f1.z * r1.z + f1.w * r1.w;

#pragma unroll
    for (int s = 1; s < 8; s <<= 1) {
        pel += __shfl_xor_sync(0xffffffffu, pel, s);
        per += __shfl_xor_sync(0xffffffffu, per, s);
    }
    if ((lane & 7) == 0) {
        g_el[node * 4 + head] = pel;
        g_er[node * 4 + head] = per;
    }
}

// ---------------------------------------------------------------------------
// Reset per-node softmax state
// ---------------------------------------------------------------------------
__global__ void reset_nd_kernel(int n4)
{
    int i = blockIdx.x * blockDim.x + threadIdx.x;
    if (i < n4) { g_emax[i] = 0u; g_denom[i] = 0.f; }
}

__global__ void zero_agg_kernel(int n256)
{
    int i = blockIdx.x * blockDim.x + threadIdx.x;
    if (i < n256) g_agg[i] = 0.f;
}

// ---------------------------------------------------------------------------
// Edge pass 1: segment max (atomicMax on order-preserving keys)
// ---------------------------------------------------------------------------
__global__ void edge_max_kernel(const int* __restrict__ src,
                                const int* __restrict__ dst, int E)
{
    int i = blockIdx.x * blockDim.x + threadIdx.x;
    if (i >= E) return;
    int s = src[i], d = dst[i];
    float4 l = *(const float4*)(g_el + (size_t)s * 4);
    float4 r = *(const float4*)(g_er + (size_t)d * 4);
    float e0 = l.x + r.x; e0 = e0 >= 0.f ? e0 : NEG_SLOPE * e0;
    float e1 = l.y + r.y; e1 = e1 >= 0.f ? e1 : NEG_SLOPE * e1;
    float e2 = l.z + r.z; e2 = e2 >= 0.f ? e2 : NEG_SLOPE * e2;
    float e3 = l.w + r.w; e3 = e3 >= 0.f ? e3 : NEG_SLOPE * e3;
    unsigned int* m = g_emax + (size_t)d * 4;
    atomicMax(m + 0, fkey(e0));
    atomicMax(m + 1, fkey(e1));
    atomicMax(m + 2, fkey(e2));
    atomicMax(m + 3, fkey(e3));
}

// ---------------------------------------------------------------------------
// Edge pass 2: ex = exp(e - max), segment sum of ex
// ---------------------------------------------------------------------------
__global__ void edge_exp_kernel(const int* __restrict__ src,
                                const int* __restrict__ dst, int E)
{
    int i = blockIdx.x * blockDim.x + threadIdx.x;
    if (i >= E) return;
    int s = src[i], d = dst[i];
    float4 l = *(const float4*)(g_el + (size_t)s * 4);
    float4 r = *(const float4*)(g_er + (size_t)d * 4);
    uint4  mk = *(const uint4*)(g_emax + (size_t)d * 4);
    float e0 = l.x + r.x; e0 = e0 >= 0.f ? e0 : NEG_SLOPE * e0;
    float e1 = l.y + r.y; e1 = e1 >= 0.f ? e1 : NEG_SLOPE * e1;
    float e2 = l.z + r.z; e2 = e2 >= 0.f ? e2 : NEG_SLOPE * e2;
    float e3 = l.w + r.w; e3 = e3 >= 0.f ? e3 : NEG_SLOPE * e3;
    float x0 = expf(e0 - fkey_dec(mk.x));
    float x1 = expf(e1 - fkey_dec(mk.y));
    float x2 = expf(e2 - fkey_dec(mk.z));
    float x3 = expf(e3 - fkey_dec(mk.w));
    float* dn = g_denom + (size_t)d * 4;
    atomicAdd(dn + 0, x0);
    atomicAdd(dn + 1, x1);
    atomicAdd(dn + 2, x2);
    atomicAdd(dn + 3, x3);
    *(float4*)(g_ex + (size_t)i * 4) = make_float4(x0, x1, x2, x3);
}

// ---------------------------------------------------------------------------
// Edge pass 3: out[dst] += alpha * feat[src]. One warp per edge.
// ---------------------------------------------------------------------------
__global__ void aggregate_kernel(const int* __restrict__ src,
                                 const int* __restrict__ dst, int E)
{
    int gt   = blockIdx.x * blockDim.x + threadIdx.x;
    int e    = gt >> 5;
    int lane = gt & 31;
    if (e >= E) return;
    int s = src[e], d = dst[e];

    float4 x4 = *(const float4*)(g_ex + (size_t)e * 4);
    float4 d4 = *(const float4*)(g_denom + (size_t)d * 4);
    float a0 = x4.x / fmaxf(d4.x, 1e-9f);
    float a1 = x4.y / fmaxf(d4.y, 1e-9f);
    float a2 = x4.z / fmaxf(d4.z, 1e-9f);
    float a3 = x4.w / fmaxf(d4.w, 1e-9f);

    int head = lane >> 3;
    float alpha = (head == 0) ? a0 : (head == 1) ? a1 : (head == 2) ? a2 : a3;

    const float4* fs = (const float4*)(g_feat + (size_t)s * 256) + lane * 2;
    float4 v0 = fs[0];
    float4 v1 = fs[1];

    float* ag = g_agg + (size_t)d * 256 + lane * 8;
    atomicAdd(ag + 0, v0.x * alpha);
    atomicAdd(ag + 1, v0.y * alpha);
    atomicAdd(ag + 2, v0.z * alpha);
    atomicAdd(ag + 3, v0.w * alpha);
    atomicAdd(ag + 4, v1.x * alpha);
    atomicAdd(ag + 5, v1.y * alpha);
    atomicAdd(ag + 6, v1.z * alpha);
    atomicAdd(ag + 7, v1.w * alpha);
}

// ---------------------------------------------------------------------------
// Epilogue: hacc (+)= elu(agg + b) / 3 ; also re-zeros agg for next relation.
// ---------------------------------------------------------------------------
__global__ void finalize_kernel(const float* __restrict__ b,
                                float* __restrict__ hacc, int first, int n256)
{
    int i = blockIdx.x * blockDim.x + threadIdx.x;
    if (i >= n256) return;
    float v = g_agg[i];
    g_agg[i] = 0.f;
    v += b[i & 255];
    v = v > 0.f ? v : expm1f(v);
    v *= (1.f / 3.f);
    if (first) hacc[i] = v; else hacc[i] += v;
}

// ---------------------------------------------------------------------------
// Final: mean over heads -> (n, 64)
// ---------------------------------------------------------------------------
__global__ void final_out_kernel(const float* __restrict__ h,
                                 float* __restrict__ out, int n)
{
    int i = blockIdx.x * blockDim.x + threadIdx.x;
    if (i >= n * 64) return;
    int node = i >> 6;
    int dd   = i & 63;
    const float* p = h + (size_t)node * 256 + dd;
    out[i] = 0.25f * (p[0] + p[64] + p[128] + p[192]);
}

// ---------------------------------------------------------------------------
// Host launch
// ---------------------------------------------------------------------------
extern "C" void kernel_launch(void* const* d_in, const int* in_sizes, int n_in,
                              void* d_out, int out_size)
{
    const float* x   = (const float*)d_in[0];
    const int*   src = (const int*)d_in[1];
    const int*   dst = (const int*)d_in[2];
    const float* W[3]  = {(const float*)d_in[3],  (const float*)d_in[7],  (const float*)d_in[11]};
    const float* al[3] = {(const float*)d_in[4],  (const float*)d_in[8],  (const float*)d_in[12]};
    const float* ar[3] = {(const float*)d_in[5],  (const float*)d_in[9],  (const float*)d_in[13]};
    const float* bb[3] = {(const float*)d_in[6],  (const float*)d_in[10], (const float*)d_in[14]};

    const int n = in_sizes[0] / FD;       // 50000
    const int E = in_sizes[1] / 3;        // 400000
    const int n256 = n * FD;

    float *bufA, *bufB;
    cudaGetSymbolAddress((void**)&bufA, g_bufA);
    cudaGetSymbolAddress((void**)&bufB, g_bufB);

    // Defensive: guarantee agg starts zeroed every launch.
    zero_agg_kernel<<<(n256 + 255) / 256, 256>>>(n256);

    const float* lay_in[3]  = {x, bufA, bufB};
    float*       lay_out[3] = {bufA, bufB, bufA};

    dim3 gemm_grid((n + 127) / 128, 2);

    for (int L = 0; L < 3; L++) {
        for (int r = 0; r < 3; r++) {
            sgemm_kernel<<<gemm_grid, 256>>>(lay_in[L], W[L] + r * 65536, n);
            attn_prep_kernel<<<(n * 32 + 255) / 256, 256>>>(al[L] + r * 256,
                                                            ar[L] + r * 256, n);
            reset_nd_kernel<<<(n * 4 + 255) / 256, 256>>>(n * 4);
            edge_max_kernel<<<(E + 255) / 256, 256>>>(src + r * E, dst + r * E, E);
            edge_exp_kernel<<<(E + 255) / 256, 256>>>(src + r * E, dst + r * E, E);
            aggregate_kernel<<<(E * 32 + 255) / 256, 256>>>(src + r * E, dst + r * E, E);
            finalize_kernel<<<(n256 + 255) / 256, 256>>>(bb[L] + r * 256,
                                                         lay_out[L], r == 0, n256);
        }
    }
    final_out_kernel<<<(n * 64 + 255) / 256, 256>>>(bufA, (float*)d_out, n);
}

// round 6
// speedup vs baseline: 3.3056x; 3.3056x over previous
#include <cuda_runtime.h>
#include <cstdint>
#include <cstddef>

// ---------------------------------------------------------------------------
// Problem constants
// ---------------------------------------------------------------------------
#define NMAX 50000
#define EMAX 400000
#define FD   256
#define NEG_SLOPE 0.2f

// ---------------------------------------------------------------------------
// Scratch (device globals — no runtime allocation allowed)
// ---------------------------------------------------------------------------
__device__ __align__(128) float g_feat[NMAX * FD];
__device__ __align__(128) float g_bufA[NMAX * FD];
__device__ __align__(128) float g_bufB[NMAX * FD];
__device__ __align__(128) float g_el[NMAX * 4];
__device__ __align__(128) float g_er[NMAX * 4];
__device__ __align__(128) int   g_deg   [3 * NMAX];
__device__ __align__(128) int   g_rowptr[3 * NMAX + 1];
__device__ __align__(128) int   g_cursor[3 * NMAX];
__device__ __align__(128) int   g_csrsrc[3 * EMAX];

// ---------------------------------------------------------------------------
// Packed f32x2 helpers (Blackwell dual-rate fp32 FMA)
// ---------------------------------------------------------------------------
__device__ __forceinline__ unsigned long long pack2(float x, float y) {
    unsigned long long r;
    asm("mov.b64 %0, {%1, %2};" : "=l"(r) : "f"(x), "f"(y));
    return r;
}
__device__ __forceinline__ void fma2(unsigned long long& d,
                                     unsigned long long a,
                                     unsigned long long b) {
    asm("fma.rn.f32x2 %0, %1, %2, %0;" : "+l"(d) : "l"(a), "l"(b));
}
__device__ __forceinline__ float2 unpack2(unsigned long long v) {
    float2 f;
    asm("mov.b64 {%0, %1}, %2;" : "=f"(f.x), "=f"(f.y) : "l"(v));
    return f;
}

// ---------------------------------------------------------------------------
// CSR build
// ---------------------------------------------------------------------------
__global__ void zero_deg_kernel(int n3)
{
    int i = blockIdx.x * blockDim.x + threadIdx.x;
    if (i < n3) g_deg[i] = 0;
}

__global__ void hist_kernel(const int* __restrict__ dst_all, int E, int n)
{
    int g = blockIdx.x * blockDim.x + threadIdx.x;
    if (g >= 3 * E) return;
    int rel = g / E;
    int d   = dst_all[g];
    atomicAdd(&g_deg[rel * n + d], 1);
}

// Single-block exclusive scan over g_deg[0..total) -> g_rowptr / g_cursor.
__global__ void scan_kernel(int total, int grand)
{
    __shared__ int warpsum[32];
    __shared__ int carry_sh;
    const int t    = threadIdx.x;      // 1024 threads
    const int lane = t & 31;
    const int wid  = t >> 5;
    if (t == 0) carry_sh = 0;
    __syncthreads();

    for (int base = 0; base < total; base += 1024) {
        int idx = base + t;
        int v   = (idx < total) ? g_deg[idx] : 0;
        int inc = v;
#pragma unroll
        for (int off = 1; off < 32; off <<= 1) {
            int x = __shfl_up_sync(0xffffffffu, inc, off);
            if (lane >= off) inc += x;
        }
        if (lane == 31) warpsum[wid] = inc;
        __syncthreads();
        if (wid == 0) {
            int w    = warpsum[lane];
            int winc = w;
#pragma unroll
            for (int off = 1; off < 32; off <<= 1) {
                int x = __shfl_up_sync(0xffffffffu, winc, off);
                if (lane >= off) winc += x;
            }
            warpsum[lane] = winc - w;   // exclusive warp offsets
        }
        __syncthreads();
        int excl = carry_sh + warpsum[wid] + inc - v;
        if (idx < total) { g_rowptr[idx] = excl; g_cursor[idx] = excl; }
        __syncthreads();
        if (t == 1023) carry_sh = carry_sh + warpsum[31] + inc;
        __syncthreads();
    }
    if (t == 0) g_rowptr[total] = grand;
}

__global__ void scatter_kernel(const int* __restrict__ src_all,
                               const int* __restrict__ dst_all, int E, int n)
{
    int g = blockIdx.x * blockDim.x + threadIdx.x;
    if (g >= 3 * E) return;
    int rel = g / E;
    int d   = dst_all[g];
    int s   = src_all[g];
    int pos = atomicAdd(&g_cursor[rel * n + d], 1);
    g_csrsrc[pos] = s;
}

// ---------------------------------------------------------------------------
// SGEMM: g_feat(n x 256) = A(n x 256) * B(256 x 256), fp32 (f32x2 packed).
// BM=BN=128, BK=16, 256 threads, 8x8 per thread (cols split colA / colA+64).
// Fused epilogue: per-row el/er attention projections via 16-lane reductions.
// ---------------------------------------------------------------------------
__global__ __launch_bounds__(256, 2)
void sgemm_kernel(const float* __restrict__ A, const float* __restrict__ B,
                  const float* __restrict__ al, const float* __restrict__ ar,
                  int nrows)
{
    __shared__ float As[16][128];   // As[k][row]
    __shared__ float Bs[16][128];   // Bs[k][col]

    const int tid  = threadIdx.x;
    const int brow = blockIdx.x * 128;
    const int bcol = blockIdx.y * 128;
    const int tx   = tid & 15;
    const int ty   = tid >> 4;
    const int row0 = ty * 8;
    const int colA = tx * 4;

    unsigned long long acc[8][4];
#pragma unroll
    for (int i = 0; i < 8; i++)
#pragma unroll
        for (int j = 0; j < 4; j++) acc[i][j] = 0ULL;

    const int fa = tid * 2;

    for (int kt = 0; kt < 256; kt += 16) {
#pragma unroll
        for (int q = 0; q < 2; q++) {
            int f  = fa + q;
            int r  = f >> 2;
            int k0 = (f & 3) * 4;
            float4 v = make_float4(0.f, 0.f, 0.f, 0.f);
            int grow = brow + r;
            if (grow < nrows)
                v = *(const float4*)(A + (size_t)grow * 256 + kt + k0);
            As[k0 + 0][r] = v.x;
            As[k0 + 1][r] = v.y;
            As[k0 + 2][r] = v.z;
            As[k0 + 3][r] = v.w;
        }
#pragma unroll
        for (int q = 0; q < 2; q++) {
            int f = fa + q;
            int k = f >> 5;
            int c = (f & 31) * 4;
            *(float4*)&Bs[k][c] =
                *(const float4*)(B + (size_t)(kt + k) * 256 + bcol + c);
        }
        __syncthreads();

#pragma unroll
        for (int k = 0; k < 16; k++) {
            float4 a0 = *(const float4*)&As[k][row0];
            float4 a1 = *(const float4*)&As[k][row0 + 4];
            unsigned long long b0 = *(const unsigned long long*)&Bs[k][colA];
            unsigned long long b1 = *(const unsigned long long*)&Bs[k][colA + 2];
            unsigned long long b2 = *(const unsigned long long*)&Bs[k][colA + 64];
            unsigned long long b3 = *(const unsigned long long*)&Bs[k][colA + 66];
            float av[8] = {a0.x, a0.y, a0.z, a0.w, a1.x, a1.y, a1.z, a1.w};
#pragma unroll
            for (int i = 0; i < 8; i++) {
                unsigned long long aa = pack2(av[i], av[i]);
                fma2(acc[i][0], aa, b0);
                fma2(acc[i][1], aa, b1);
                fma2(acc[i][2], aa, b2);
                fma2(acc[i][3], aa, b3);
            }
        }
        __syncthreads();
    }

    // Attention weight slices for this thread's columns. Heads h0 = bcol/64
    // (cols colA..colA+3) and h0+1 (cols colA+64..colA+67). al[bcol+colA]
    // is exactly head h0's weights at offset colA.
    const int h0 = bcol >> 6;
    float4 AL0 = *(const float4*)(al + bcol + colA);
    float4 AL1 = *(const float4*)(al + bcol + 64 + colA);
    float4 AR0 = *(const float4*)(ar + bcol + colA);
    float4 AR1 = *(const float4*)(ar + bcol + 64 + colA);

#pragma unroll
    for (int i = 0; i < 8; i++) {
        int grow = brow + row0 + i;
        float2 c0 = unpack2(acc[i][0]);
        float2 c1 = unpack2(acc[i][1]);
        float2 c2 = unpack2(acc[i][2]);
        float2 c3 = unpack2(acc[i][3]);
        if (grow < nrows) {
            float* C = g_feat + (size_t)grow * 256 + bcol;
            *(float4*)(C + colA)      = make_float4(c0.x, c0.y, c1.x, c1.y);
            *(float4*)(C + colA + 64) = make_float4(c2.x, c2.y, c3.x, c3.y);
        }
        // partial dot with attention vectors (OOB rows hold zeros -> harmless)
        float pel0 = c0.x * AL0.x + c0.y * AL0.y + c1.x * AL0.z + c1.y * AL0.w;
        float pel1 = c2.x * AL1.x + c2.y * AL1.y + c3.x * AL1.z + c3.y * AL1.w;
        float per0 = c0.x * AR0.x + c0.y * AR0.y + c1.x * AR0.z + c1.y * AR0.w;
        float per1 = c2.x * AR1.x + c2.y * AR1.y + c3.x * AR1.z + c3.y * AR1.w;
#pragma unroll
        for (int s = 1; s < 16; s <<= 1) {
            pel0 += __shfl_xor_sync(0xffffffffu, pel0, s);
            pel1 += __shfl_xor_sync(0xffffffffu, pel1, s);
            per0 += __shfl_xor_sync(0xffffffffu, per0, s);
            per1 += __shfl_xor_sync(0xffffffffu, per1, s);
        }
        if (tx == 0 && grow < nrows) {
            g_el[grow * 4 + h0]     = pel0;
            g_el[grow * 4 + h0 + 1] = pel1;
            g_er[grow * 4 + h0]     = per0;
            g_er[grow * 4 + h0 + 1] = per1;
        }
    }
}

// ---------------------------------------------------------------------------
// Node-centric softmax + aggregation. One warp per dst node.
//   mode 0: hacc  = elu(agg + b)/3
//   mode 1: hacc += elu(agg + b)/3
//   mode 2: (last rel of last layer) head-mean of (hacc + elu(agg+b)/3) -> out
// ---------------------------------------------------------------------------
__device__ __forceinline__ float lrelu(float e) {
    return e >= 0.f ? e : NEG_SLOPE * e;
}

__global__ __launch_bounds__(256)
void node_agg_kernel(const float* __restrict__ bias,
                     float* __restrict__ hacc,
                     float* __restrict__ outp,
                     int mode, int rbase, int n)
{
    const int warp = (blockIdx.x * blockDim.x + threadIdx.x) >> 5;
    const int lane = threadIdx.x & 31;
    if (warp >= n) return;
    const int node = warp;
    const int beg  = g_rowptr[rbase + node];
    const int end  = g_rowptr[rbase + node + 1];

    const float4 er4 = *(const float4*)(g_er + (size_t)node * 4);

    // ---- pass 1: per-head max over incoming edges ----
    float4 m = make_float4(-3.4e38f, -3.4e38f, -3.4e38f, -3.4e38f);
    for (int i = beg + lane; i < end; i += 32) {
        int s = g_csrsrc[i];
        float4 l = *(const float4*)(g_el + (size_t)s * 4);
        m.x = fmaxf(m.x, lrelu(l.x + er4.x));
        m.y = fmaxf(m.y, lrelu(l.y + er4.y));
        m.z = fmaxf(m.z, lrelu(l.z + er4.z));
        m.w = fmaxf(m.w, lrelu(l.w + er4.w));
    }
#pragma unroll
    for (int s_ = 16; s_; s_ >>= 1) {
        m.x = fmaxf(m.x, __shfl_xor_sync(0xffffffffu, m.x, s_));
        m.y = fmaxf(m.y, __shfl_xor_sync(0xffffffffu, m.y, s_));
        m.z = fmaxf(m.z, __shfl_xor_sync(0xffffffffu, m.z, s_));
        m.w = fmaxf(m.w, __shfl_xor_sync(0xffffffffu, m.w, s_));
    }

    // ---- pass 2: sum of exp(e - max) ----
    float4 ss = make_float4(0.f, 0.f, 0.f, 0.f);
    for (int i = beg + lane; i < end; i += 32) {
        int s = g_csrsrc[i];
        float4 l = *(const float4*)(g_el + (size_t)s * 4);
        ss.x += expf(lrelu(l.x + er4.x) - m.x);
        ss.y += expf(lrelu(l.y + er4.y) - m.y);
        ss.z += expf(lrelu(l.z + er4.z) - m.z);
        ss.w += expf(lrelu(l.w + er4.w) - m.w);
    }
#pragma unroll
    for (int s_ = 16; s_; s_ >>= 1) {
        ss.x += __shfl_xor_sync(0xffffffffu, ss.x, s_);
        ss.y += __shfl_xor_sync(0xffffffffu, ss.y, s_);
        ss.z += __shfl_xor_sync(0xffffffffu, ss.z, s_);
        ss.w += __shfl_xor_sync(0xffffffffu, ss.w, s_);
    }

    const int head = lane >> 3;
    float mh = (head == 0) ? m.x : (head == 1) ? m.y : (head == 2) ? m.z : m.w;
    float sh = (head == 0) ? ss.x : (head == 1) ? ss.y : (head == 2) ? ss.z : ss.w;
    float eh = (head == 0) ? er4.x : (head == 1) ? er4.y : (head == 2) ? er4.z : er4.w;
    float rh = 1.f / fmaxf(sh, 1e-9f);

    // ---- pass 3: feature accumulation (whole warp per edge) ----
    float4 a0 = make_float4(0.f, 0.f, 0.f, 0.f);
    float4 a1 = make_float4(0.f, 0.f, 0.f, 0.f);
    for (int i = beg; i < end; i++) {
        int s = g_csrsrc[i];                    // broadcast
        float alpha = expf(lrelu(g_el[(size_t)s * 4 + head] + eh) - mh) * rh;
        const float4* fs = (const float4*)(g_feat + (size_t)s * 256) + lane * 2;
        float4 v0 = fs[0];
        float4 v1 = fs[1];
        a0.x += v0.x * alpha; a0.y += v0.y * alpha;
        a0.z += v0.z * alpha; a0.w += v0.w * alpha;
        a1.x += v1.x * alpha; a1.y += v1.y * alpha;
        a1.z += v1.z * alpha; a1.w += v1.w * alpha;
    }

    // ---- epilogue: bias + elu + /3, cross-relation accumulate ----
    const int col = lane * 8;
    float4 b0 = *(const float4*)(bias + col);
    float4 b1 = *(const float4*)(bias + col + 4);
    float v[8];
    v[0] = a0.x + b0.x; v[1] = a0.y + b0.y; v[2] = a0.z + b0.z; v[3] = a0.w + b0.w;
    v[4] = a1.x + b1.x; v[5] = a1.y + b1.y; v[6] = a1.z + b1.z; v[7] = a1.w + b1.w;
#pragma unroll
    for (int j = 0; j < 8; j++) {
        float t = v[j];
        v[j] = (t > 0.f ? t : expm1f(t)) * (1.f / 3.f);
    }

    float* hp = hacc + (size_t)node * 256 + col;
    if (mode == 0) {
        *(float4*)(hp)     = make_float4(v[0], v[1], v[2], v[3]);
        *(float4*)(hp + 4) = make_float4(v[4], v[5], v[6], v[7]);
    } else if (mode == 1) {
        float4 p0 = *(const float4*)(hp);
        float4 p1 = *(const float4*)(hp + 4);
        *(float4*)(hp)     = make_float4(p0.x + v[0], p0.y + v[1], p0.z + v[2], p0.w + v[3]);
        *(float4*)(hp + 4) = make_float4(p1.x + v[4], p1.y + v[5], p1.z + v[6], p1.w + v[7]);
    } else {
        // last relation of last layer: total = hacc + v, then mean over heads
        float4 p0 = *(const float4*)(hp);
        float4 p1 = *(const float4*)(hp + 4);
        v[0] += p0.x; v[1] += p0.y; v[2] += p0.z; v[3] += p0.w;
        v[4] += p1.x; v[5] += p1.y; v[6] += p1.z; v[7] += p1.w;
#pragma unroll
        for (int j = 0; j < 8; j++) {
            v[j] += __shfl_xor_sync(0xffffffffu, v[j], 8);
            v[j] += __shfl_xor_sync(0xffffffffu, v[j], 16);
        }
        if (lane < 8) {
            float* o = outp + (size_t)node * 64 + lane * 8;
#pragma unroll
            for (int j = 0; j < 8; j++) o[j] = 0.25f * v[j];
        }
    }
}

// ---------------------------------------------------------------------------
// Host launch
// ---------------------------------------------------------------------------
extern "C" void kernel_launch(void* const* d_in, const int* in_sizes, int n_in,
                              void* d_out, int out_size)
{
    const float* x   = (const float*)d_in[0];
    const int*   src = (const int*)d_in[1];
    const int*   dst = (const int*)d_in[2];
    const float* W[3]  = {(const float*)d_in[3],  (const float*)d_in[7],  (const float*)d_in[11]};
    const float* al[3] = {(const float*)d_in[4],  (const float*)d_in[8],  (const float*)d_in[12]};
    const float* ar[3] = {(const float*)d_in[5],  (const float*)d_in[9],  (const float*)d_in[13]};
    const float* bb[3] = {(const float*)d_in[6],  (const float*)d_in[10], (const float*)d_in[14]};

    const int n = in_sizes[0] / FD;    // 50000
    const int E = in_sizes[1] / 3;     // 400000

    float *bufA, *bufB;
    cudaGetSymbolAddress((void**)&bufA, g_bufA);
    cudaGetSymbolAddress((void**)&bufB, g_bufB);

    // ---- CSR build (per launch; uses only the constant edge lists) ----
    zero_deg_kernel<<<(3 * n + 255) / 256, 256>>>(3 * n);
    hist_kernel<<<(3 * E + 255) / 256, 256>>>(dst, E, n);
    scan_kernel<<<1, 1024>>>(3 * n, 3 * E);
    scatter_kernel<<<(3 * E + 255) / 256, 256>>>(src, dst, E, n);

    const float* lay_in[3]  = {x, bufA, bufB};
    float*       lay_out[3] = {bufA, bufB, bufA};

    dim3 gemm_grid((n + 127) / 128, 2);
    int  agg_blocks = (n + 7) / 8;     // 8 warps (nodes) per 256-thread block

    for (int L = 0; L < 3; L++) {
        for (int r = 0; r < 3; r++) {
            sgemm_kernel<<<gemm_grid, 256>>>(lay_in[L], W[L] + r * 65536,
                                             al[L] + r * 256, ar[L] + r * 256, n);
            int mode = (r == 0) ? 0 : ((L == 2 && r == 2) ? 2 : 1);
            node_agg_kernel<<<agg_blocks, 256>>>(bb[L] + r * 256, lay_out[L],
                                                 (float*)d_out, mode, r * n, n);
        }
    }
}

// round 8
// speedup vs baseline: 5.3855x; 1.6292x over previous
#include <cuda_runtime.h>
#include <cuda_bf16.h>
#include <cstdint>
#include <cstddef>

// ---------------------------------------------------------------------------
// Problem constants
// ---------------------------------------------------------------------------
#define NMAX 50000
#define NPAD 50048            // 391 * 128
#define EMAX 400000
#define FD   256
#define NEG_SLOPE 0.2f

// ---------------------------------------------------------------------------
// Scratch (device globals — no runtime allocation allowed)
// ---------------------------------------------------------------------------
__device__ __align__(128) float g_feat[NPAD * FD];
__device__ __align__(128) float g_bufA[NMAX * FD];
__device__ __align__(128) float g_bufB[NMAX * FD];
__device__ __align__(128) float g_el[NPAD * 4];
__device__ __align__(128) float g_er[NPAD * 4];
__device__ __align__(128) int   g_deg   [3 * NMAX];
__device__ __align__(128) int   g_rowptr[3 * NMAX + 1];
__device__ __align__(128) int   g_cursor[3 * NMAX];
__device__ __align__(128) int   g_csrsrc[3 * EMAX];
// bf16 split operands
__device__ __align__(128) __nv_bfloat16 g_Ah[NPAD * FD];
__device__ __align__(128) __nv_bfloat16 g_Al[NPAD * FD];
__device__ __align__(128) __nv_bfloat16 g_Wh[9 * FD * FD];   // [mat][n][k]
__device__ __align__(128) __nv_bfloat16 g_Wl[9 * FD * FD];

// ---------------------------------------------------------------------------
// PTX helpers (portable subset only — no sm_103a-suffixed features)
// ---------------------------------------------------------------------------
__device__ __forceinline__ uint32_t smem_u32(const void* p) {
    uint32_t a;
    asm("{ .reg .u64 t; cvta.to.shared.u64 t, %1; cvt.u32.u64 %0, t; }"
        : "=r"(a) : "l"(p));
    return a;
}

#define LDM_X4(r0, r1, r2, r3, a) \
    asm volatile("ldmatrix.sync.aligned.m8n8.x4.shared.b16 {%0,%1,%2,%3}, [%4];" \
                 : "=r"(r0), "=r"(r1), "=r"(r2), "=r"(r3) : "r"(a))
#define LDM_X2(r0, r1, a) \
    asm volatile("ldmatrix.sync.aligned.m8n8.x2.shared.b16 {%0,%1}, [%2];" \
                 : "=r"(r0), "=r"(r1) : "r"(a))
#define MMA_BF16(d, a, b) \
    asm volatile("mma.sync.aligned.m16n8k16.row.col.f32.bf16.bf16.f32 " \
                 "{%0,%1,%2,%3}, {%4,%5,%6,%7}, {%8,%9}, {%0,%1,%2,%3};" \
                 : "+f"((d)[0]), "+f"((d)[1]), "+f"((d)[2]), "+f"((d)[3]) \
                 : "r"((a)[0]), "r"((a)[1]), "r"((a)[2]), "r"((a)[3]), \
                   "r"((b)[0]), "r"((b)[1]))

// ---------------------------------------------------------------------------
// bf16 split conversion kernels
// ---------------------------------------------------------------------------
union U2 { ushort u[4]; uint2 v; };

__global__ void cvt_feat_kernel(const float* __restrict__ in, int n)
{
    int idx = blockIdx.x * blockDim.x + threadIdx.x;   // one float4 per thread
    if (idx >= NPAD * 64) return;
    int row = idx >> 6;
    int c4  = (idx & 63) * 4;
    float4 v = make_float4(0.f, 0.f, 0.f, 0.f);
    if (row < n) v = *(const float4*)(in + (size_t)row * 256 + c4);
    float f[4] = {v.x, v.y, v.z, v.w};
    U2 hi, lo;
#pragma unroll
    for (int j = 0; j < 4; j++) {
        __nv_bfloat16 h = __float2bfloat16(f[j]);
        __nv_bfloat16 l = __float2bfloat16(f[j] - __bfloat162float(h));
        hi.u[j] = *(ushort*)&h;
        lo.u[j] = *(ushort*)&l;
    }
    *(uint2*)(g_Ah + (size_t)row * 256 + c4) = hi.v;
    *(uint2*)(g_Al + (size_t)row * 256 + c4) = lo.v;
}

// weights: input fp32 [k][n] row-major -> output bf16 [n][k] (transposed)
__global__ void cvt_weight_kernel(const float* __restrict__ W0,
                                  const float* __restrict__ W1,
                                  const float* __restrict__ W2)
{
    int idx = blockIdx.x * blockDim.x + threadIdx.x;   // 4 k-elems per thread
    if (idx >= 9 * 256 * 64) return;
    int mat = idx / (256 * 64);
    int rem = idx % (256 * 64);
    int nn  = rem & 255;
    int k0  = (rem >> 8) * 4;
    const float* W = (mat < 3 ? W0 : mat < 6 ? W1 : W2) + (mat % 3) * 65536;
    U2 hi, lo;
#pragma unroll
    for (int j = 0; j < 4; j++) {
        float f = W[(size_t)(k0 + j) * 256 + nn];
        __nv_bfloat16 h = __float2bfloat16(f);
        __nv_bfloat16 l = __float2bfloat16(f - __bfloat162float(h));
        hi.u[j] = *(ushort*)&h;
        lo.u[j] = *(ushort*)&l;
    }
    *(uint2*)(g_Wh + (size_t)mat * 65536 + (size_t)nn * 256 + k0) = hi.v;
    *(uint2*)(g_Wl + (size_t)mat * 65536 + (size_t)nn * 256 + k0) = lo.v;
}

// ---------------------------------------------------------------------------
// mma.sync GEMM: C(128 x 128 per CTA) = A(128 x 256) * B^T(128n x 256k)
// bf16 3-term split (AhBh + AhBl + AlBh), fused el/er epilogue.
// Grid (391, 2). 8 warps: warp tile 64x32 (wr = wid&1, wc = wid>>2... see below)
// ---------------------------------------------------------------------------
#define STR 72                        // smem row stride in bf16 (144 B)
#define TILE_B (128 * STR)            // bf16 elements per buffer
#define GEMM_SMEM (4 * TILE_B * 2)    // 73728 bytes

__global__ __launch_bounds__(256, 2)
void gemm_mma_kernel(const __nv_bfloat16* __restrict__ Ah,
                     const __nv_bfloat16* __restrict__ Al,
                     const __nv_bfloat16* __restrict__ Bh,
                     const __nv_bfloat16* __restrict__ Bl,
                     const float* __restrict__ alw,
                     const float* __restrict__ arw,
                     int nrows)
{
    extern __shared__ __nv_bfloat16 sm[];
    __nv_bfloat16* sAh = sm;
    __nv_bfloat16* sAl = sm + TILE_B;
    __nv_bfloat16* sBh = sm + 2 * TILE_B;
    __nv_bfloat16* sBl = sm + 3 * TILE_B;

    const int tid  = threadIdx.x;
    const int wid  = tid >> 5;
    const int lane = tid & 31;
    const int wr   = wid & 1;         // 0/1 -> rows [0,64) / [64,128)
    const int wc   = wid >> 1;        // 0..3 -> cols [wc*32, wc*32+32)
    const int brow = blockIdx.x * 128;
    const int bcol = blockIdx.y * 128;

    const uint32_t sAh32 = smem_u32(sAh);
    const uint32_t sAl32 = smem_u32(sAl);
    const uint32_t sBh32 = smem_u32(sBh);
    const uint32_t sBl32 = smem_u32(sBl);

    float acc[4][4][4];               // [ma][na][frag]
#pragma unroll
    for (int i = 0; i < 4; i++)
#pragma unroll
        for (int j = 0; j < 4; j++)
#pragma unroll
            for (int q = 0; q < 4; q++) acc[i][j][q] = 0.f;

    const uint4* A4h = (const uint4*)Ah;
    const uint4* A4l = (const uint4*)Al;
    const uint4* B4h = (const uint4*)Bh;
    const uint4* B4l = (const uint4*)Bl;

    // lane-derived ldmatrix address components
    const int a_r  = (lane & 7) + ((lane >> 3) & 1) * 8;   // row within atom
    const int a_k8 = (lane >> 4) * 8;                      // k half
    const int b_n  = (lane & 15) & 7;                      // row within 8x8
    const int b_k8 = (((lane & 15) >> 3) & 1) * 8;

    for (int kc = 0; kc < 4; kc++) {
        __syncthreads();
        // ---- stage tiles: 128 rows x 64 k each (4 uint4 per thread per tile)
#pragma unroll
        for (int j = 0; j < 4; j++) {
            int i   = tid + j * 256;          // 0..1023
            int row = i >> 3, u = i & 7;
            size_t ga = (size_t)(brow + row) * 32 + kc * 8 + u;
            size_t gb = (size_t)(bcol + row) * 32 + kc * 8 + u;
            uint32_t so = (uint32_t)(row * STR + u * 8);
            *(uint4*)(sAh + so) = A4h[ga];
            *(uint4*)(sAl + so) = A4l[ga];
            *(uint4*)(sBh + so) = B4h[gb];
            *(uint4*)(sBl + so) = B4l[gb];
        }
        __syncthreads();

#pragma unroll
        for (int ks = 0; ks < 4; ks++) {
            const int k0 = ks * 16;
            uint32_t afr[4][4], bh[4][2], bl[4][2];
            // A (hi) fragments
#pragma unroll
            for (int ma = 0; ma < 4; ma++) {
                uint32_t addr = sAh32 +
                    (uint32_t)(((wr * 64 + ma * 16 + a_r) * STR + k0 + a_k8) * 2);
                LDM_X4(afr[ma][0], afr[ma][1], afr[ma][2], afr[ma][3], addr);
            }
            // B (hi, lo) fragments
#pragma unroll
            for (int na = 0; na < 4; na++) {
                uint32_t off = (uint32_t)(((wc * 32 + na * 8 + b_n) * STR + k0 + b_k8) * 2);
                LDM_X2(bh[na][0], bh[na][1], sBh32 + off);
                LDM_X2(bl[na][0], bl[na][1], sBl32 + off);
            }
            // AhBh + AhBl
#pragma unroll
            for (int ma = 0; ma < 4; ma++)
#pragma unroll
                for (int na = 0; na < 4; na++) {
                    MMA_BF16(acc[ma][na], afr[ma], bh[na]);
                    MMA_BF16(acc[ma][na], afr[ma], bl[na]);
                }
            // reload A (lo) over the same registers, AlBh
#pragma unroll
            for (int ma = 0; ma < 4; ma++) {
                uint32_t addr = sAl32 +
                    (uint32_t)(((wr * 64 + ma * 16 + a_r) * STR + k0 + a_k8) * 2);
                LDM_X4(afr[ma][0], afr[ma][1], afr[ma][2], afr[ma][3], addr);
            }
#pragma unroll
            for (int ma = 0; ma < 4; ma++)
#pragma unroll
                for (int na = 0; na < 4; na++)
                    MMA_BF16(acc[ma][na], afr[ma], bh[na]);
        }
    }

    // ------------------------------------------------------------------
    // Epilogue. acc frag layout: d0=(r,c) d1=(r,c+1) d2=(r+8,c) d3=(r+8,c+1)
    // where r = wr*64 + ma*16 + lane/4, c = wc*32 + na*8 + (lane%4)*2.
    // ------------------------------------------------------------------
    // attention weights for this thread's columns (warp is within ONE head)
    float alv[4][2], arv[4][2];
#pragma unroll
    for (int na = 0; na < 4; na++) {
        int gc = bcol + wc * 32 + na * 8 + (lane & 3) * 2;
        alv[na][0] = alw[gc];     alv[na][1] = alw[gc + 1];
        arv[na][0] = arw[gc];     arv[na][1] = arw[gc + 1];
    }

    float pel[4][2], per_[4][2];
#pragma unroll
    for (int ma = 0; ma < 4; ma++) {
        pel[ma][0] = pel[ma][1] = per_[ma][0] = per_[ma][1] = 0.f;
#pragma unroll
        for (int na = 0; na < 4; na++) {
            pel[ma][0]  += acc[ma][na][0] * alv[na][0] + acc[ma][na][1] * alv[na][1];
            pel[ma][1]  += acc[ma][na][2] * alv[na][0] + acc[ma][na][3] * alv[na][1];
            per_[ma][0] += acc[ma][na][0] * arv[na][0] + acc[ma][na][1] * arv[na][1];
            per_[ma][1] += acc[ma][na][2] * arv[na][0] + acc[ma][na][3] * arv[na][1];
        }
#pragma unroll
        for (int s = 1; s < 4; s <<= 1) {
            pel[ma][0]  += __shfl_xor_sync(0xffffffffu, pel[ma][0],  s);
            pel[ma][1]  += __shfl_xor_sync(0xffffffffu, pel[ma][1],  s);
            per_[ma][0] += __shfl_xor_sync(0xffffffffu, per_[ma][0], s);
            per_[ma][1] += __shfl_xor_sync(0xffffffffu, per_[ma][1], s);
        }
    }

    // C store (direct from registers; rows beyond nrows dropped)
#pragma unroll
    for (int ma = 0; ma < 4; ma++) {
        int r    = wr * 64 + ma * 16 + (lane >> 2);
        int g0   = brow + r;
        int g1   = g0 + 8;
#pragma unroll
        for (int na = 0; na < 4; na++) {
            int c = bcol + wc * 32 + na * 8 + (lane & 3) * 2;
            if (g0 < nrows)
                *(float2*)(g_feat + (size_t)g0 * 256 + c) =
                    make_float2(acc[ma][na][0], acc[ma][na][1]);
            if (g1 < nrows)
                *(float2*)(g_feat + (size_t)g1 * 256 + c) =
                    make_float2(acc[ma][na][2], acc[ma][na][3]);
        }
    }

    // cross-warp combine of el/er halves (two warps per head)
    __syncthreads();                      // smem tiles no longer needed
    float* sPEl = (float*)sm;             // [4][128]
    float* sPEr = (float*)sm + 512;       // [4][128]
    if ((lane & 3) == 0) {
#pragma unroll
        for (int ma = 0; ma < 4; ma++) {
            int r = wr * 64 + ma * 16 + (lane >> 2);
            sPEl[wc * 128 + r]     = pel[ma][0];
            sPEl[wc * 128 + r + 8] = pel[ma][1];
            sPEr[wc * 128 + r]     = per_[ma][0];
            sPEr[wc * 128 + r + 8] = per_[ma][1];
        }
    }
    __syncthreads();
    if (tid < 128) {
        int grow = brow + tid;
        if (grow < nrows) {
            int h0 = blockIdx.y * 2;
            g_el[(size_t)grow * 4 + h0]     = sPEl[tid]       + sPEl[128 + tid];
            g_el[(size_t)grow * 4 + h0 + 1] = sPEl[256 + tid] + sPEl[384 + tid];
            g_er[(size_t)grow * 4 + h0]     = sPEr[tid]       + sPEr[128 + tid];
            g_er[(size_t)grow * 4 + h0 + 1] = sPEr[256 + tid] + sPEr[384 + tid];
        }
    }
}

// ---------------------------------------------------------------------------
// CSR build
// ---------------------------------------------------------------------------
__global__ void zero_deg_kernel(int n3)
{
    int i = blockIdx.x * blockDim.x + threadIdx.x;
    if (i < n3) g_deg[i] = 0;
}

__global__ void hist_kernel(const int* __restrict__ dst_all, int E, int n)
{
    int g = blockIdx.x * blockDim.x + threadIdx.x;
    if (g >= 3 * E) return;
    int rel = g / E;
    atomicAdd(&g_deg[rel * n + dst_all[g]], 1);
}

__global__ void scan_kernel(int total, int grand)
{
    __shared__ int warpsum[32];
    __shared__ int carry_sh;
    const int t    = threadIdx.x;      // 1024 threads
    const int lane = t & 31;
    const int wid  = t >> 5;
    if (t == 0) carry_sh = 0;
    __syncthreads();

    for (int base = 0; base < total; base += 1024) {
        int idx = base + t;
        int v   = (idx < total) ? g_deg[idx] : 0;
        int inc = v;
#pragma unroll
        for (int off = 1; off < 32; off <<= 1) {
            int x = __shfl_up_sync(0xffffffffu, inc, off);
            if (lane >= off) inc += x;
        }
        if (lane == 31) warpsum[wid] = inc;
        __syncthreads();
        if (wid == 0) {
            int w    = warpsum[lane];
            int winc = w;
#pragma unroll
            for (int off = 1; off < 32; off <<= 1) {
                int x = __shfl_up_sync(0xffffffffu, winc, off);
                if (lane >= off) winc += x;
            }
            warpsum[lane] = winc - w;
        }
        __syncthreads();
        int excl = carry_sh + warpsum[wid] + inc - v;
        if (idx < total) { g_rowptr[idx] = excl; g_cursor[idx] = excl; }
        __syncthreads();
        if (t == 1023) carry_sh = carry_sh + warpsum[31] + inc;
        __syncthreads();
    }
    if (t == 0) g_rowptr[total] = grand;
}

__global__ void scatter_kernel(const int* __restrict__ src_all,
                               const int* __restrict__ dst_all, int E, int n)
{
    int g = blockIdx.x * blockDim.x + threadIdx.x;
    if (g >= 3 * E) return;
    int rel = g / E;
    int pos = atomicAdd(&g_cursor[rel * n + dst_all[g]], 1);
    g_csrsrc[pos] = src_all[g];
}

// ---------------------------------------------------------------------------
// Node-centric softmax + aggregation. One warp per dst node.
// ---------------------------------------------------------------------------
__device__ __forceinline__ float lrelu(float e) {
    return e >= 0.f ? e : NEG_SLOPE * e;
}

__global__ __launch_bounds__(256)
void node_agg_kernel(const float* __restrict__ bias,
                     float* __restrict__ hacc,
                     float* __restrict__ outp,
                     int mode, int rbase, int n)
{
    const int warp = (blockIdx.x * blockDim.x + threadIdx.x) >> 5;
    const int lane = threadIdx.x & 31;
    if (warp >= n) return;
    const int node = warp;
    const int beg  = g_rowptr[rbase + node];
    const int end  = g_rowptr[rbase + node + 1];

    const float4 er4 = *(const float4*)(g_er + (size_t)node * 4);

    float4 m = make_float4(-3.4e38f, -3.4e38f, -3.4e38f, -3.4e38f);
    for (int i = beg + lane; i < end; i += 32) {
        int s = g_csrsrc[i];
        float4 l = *(const float4*)(g_el + (size_t)s * 4);
        m.x = fmaxf(m.x, lrelu(l.x + er4.x));
        m.y = fmaxf(m.y, lrelu(l.y + er4.y));
        m.z = fmaxf(m.z, lrelu(l.z + er4.z));
        m.w = fmaxf(m.w, lrelu(l.w + er4.w));
    }
#pragma unroll
    for (int s_ = 16; s_; s_ >>= 1) {
        m.x = fmaxf(m.x, __shfl_xor_sync(0xffffffffu, m.x, s_));
        m.y = fmaxf(m.y, __shfl_xor_sync(0xffffffffu, m.y, s_));
        m.z = fmaxf(m.z, __shfl_xor_sync(0xffffffffu, m.z, s_));
        m.w = fmaxf(m.w, __shfl_xor_sync(0xffffffffu, m.w, s_));
    }

    float4 ss = make_float4(0.f, 0.f, 0.f, 0.f);
    for (int i = beg + lane; i < end; i += 32) {
        int s = g_csrsrc[i];
        float4 l = *(const float4*)(g_el + (size_t)s * 4);
        ss.x += expf(lrelu(l.x + er4.x) - m.x);
        ss.y += expf(lrelu(l.y + er4.y) - m.y);
        ss.z += expf(lrelu(l.z + er4.z) - m.z);
        ss.w += expf(lrelu(l.w + er4.w) - m.w);
    }
#pragma unroll
    for (int s_ = 16; s_; s_ >>= 1) {
        ss.x += __shfl_xor_sync(0xffffffffu, ss.x, s_);
        ss.y += __shfl_xor_sync(0xffffffffu, ss.y, s_);
        ss.z += __shfl_xor_sync(0xffffffffu, ss.z, s_);
        ss.w += __shfl_xor_sync(0xffffffffu, ss.w, s_);
    }

    const int head = lane >> 3;
    float mh = (head == 0) ? m.x : (head == 1) ? m.y : (head == 2) ? m.z : m.w;
    float sh = (head == 0) ? ss.x : (head == 1) ? ss.y : (head == 2) ? ss.z : ss.w;
    float eh = (head == 0) ? er4.x : (head == 1) ? er4.y : (head == 2) ? er4.z : er4.w;
    float rh = 1.f / fmaxf(sh, 1e-9f);

    float4 a0 = make_float4(0.f, 0.f, 0.f, 0.f);
    float4 a1 = make_float4(0.f, 0.f, 0.f, 0.f);
    for (int i = beg; i < end; i++) {
        int s = g_csrsrc[i];
        float alpha = expf(lrelu(g_el[(size_t)s * 4 + head] + eh) - mh) * rh;
        const float4* fs = (const float4*)(g_feat + (size_t)s * 256) + lane * 2;
        float4 v0 = fs[0];
        float4 v1 = fs[1];
        a0.x += v0.x * alpha; a0.y += v0.y * alpha;
        a0.z += v0.z * alpha; a0.w += v0.w * alpha;
        a1.x += v1.x * alpha; a1.y += v1.y * alpha;
        a1.z += v1.z * alpha; a1.w += v1.w * alpha;
    }

    const int col = lane * 8;
    float4 b0 = *(const float4*)(bias + col);
    float4 b1 = *(const float4*)(bias + col + 4);
    float v[8];
    v[0] = a0.x + b0.x; v[1] = a0.y + b0.y; v[2] = a0.z + b0.z; v[3] = a0.w + b0.w;
    v[4] = a1.x + b1.x; v[5] = a1.y + b1.y; v[6] = a1.z + b1.z; v[7] = a1.w + b1.w;
#pragma unroll
    for (int j = 0; j < 8; j++) {
        float t = v[j];
        v[j] = (t > 0.f ? t : expm1f(t)) * (1.f / 3.f);
    }

    float* hp = hacc + (size_t)node * 256 + col;
    if (mode == 0) {
        *(float4*)(hp)     = make_float4(v[0], v[1], v[2], v[3]);
        *(float4*)(hp + 4) = make_float4(v[4], v[5], v[6], v[7]);
    } else if (mode == 1) {
        float4 p0 = *(const float4*)(hp);
        float4 p1 = *(const float4*)(hp + 4);
        *(float4*)(hp)     = make_float4(p0.x + v[0], p0.y + v[1], p0.z + v[2], p0.w + v[3]);
        *(float4*)(hp + 4) = make_float4(p1.x + v[4], p1.y + v[5], p1.z + v[6], p1.w + v[7]);
    } else {
        float4 p0 = *(const float4*)(hp);
        float4 p1 = *(const float4*)(hp + 4);
        v[0] += p0.x; v[1] += p0.y; v[2] += p0.z; v[3] += p0.w;
        v[4] += p1.x; v[5] += p1.y; v[6] += p1.z; v[7] += p1.w;
#pragma unroll
        for (int j = 0; j < 8; j++) {
            v[j] += __shfl_xor_sync(0xffffffffu, v[j], 8);
            v[j] += __shfl_xor_sync(0xffffffffu, v[j], 16);
        }
        if (lane < 8) {
            float* o = outp + (size_t)node * 64 + lane * 8;
#pragma unroll
            for (int j = 0; j < 8; j++) o[j] = 0.25f * v[j];
        }
    }
}

// ---------------------------------------------------------------------------
// Host launch
// ---------------------------------------------------------------------------
extern "C" void kernel_launch(void* const* d_in, const int* in_sizes, int n_in,
                              void* d_out, int out_size)
{
    const float* x   = (const float*)d_in[0];
    const int*   src = (const int*)d_in[1];
    const int*   dst = (const int*)d_in[2];
    const float* W[3]  = {(const float*)d_in[3],  (const float*)d_in[7],  (const float*)d_in[11]};
    const float* al[3] = {(const float*)d_in[4],  (const float*)d_in[8],  (const float*)d_in[12]};
    const float* ar[3] = {(const float*)d_in[5],  (const float*)d_in[9],  (const float*)d_in[13]};
    const float* bb[3] = {(const float*)d_in[6],  (const float*)d_in[10], (const float*)d_in[14]};

    const int n = in_sizes[0] / FD;    // 50000
    const int E = in_sizes[1] / 3;     // 400000

    cudaFuncSetAttribute(gemm_mma_kernel,
                         cudaFuncAttributeMaxDynamicSharedMemorySize, GEMM_SMEM);

    float *bufA, *bufB;
    cudaGetSymbolAddress((void**)&bufA, g_bufA);
    cudaGetSymbolAddress((void**)&bufB, g_bufB);
    __nv_bfloat16 *pAh, *pAl, *pWh, *pWl;
    cudaGetSymbolAddress((void**)&pAh, g_Ah);
    cudaGetSymbolAddress((void**)&pAl, g_Al);
    cudaGetSymbolAddress((void**)&pWh, g_Wh);
    cudaGetSymbolAddress((void**)&pWl, g_Wl);

    // weight split (once) + CSR build
    cvt_weight_kernel<<<(9 * 256 * 64 + 255) / 256, 256>>>(W[0], W[1], W[2]);
    zero_deg_kernel<<<(3 * n + 255) / 256, 256>>>(3 * n);
    hist_kernel<<<(3 * E + 255) / 256, 256>>>(dst, E, n);
    scan_kernel<<<1, 1024>>>(3 * n, 3 * E);
    scatter_kernel<<<(3 * E + 255) / 256, 256>>>(src, dst, E, n);

    const float* lay_in[3]  = {x, bufA, bufB};
    float*       lay_out[3] = {bufA, bufB, bufA};

    const dim3 gemm_grid(NPAD / 128, 2);        // (391, 2)
    const int  agg_blocks = (n + 7) / 8;
    const int  cvt_blocks = (NPAD * 64 + 255) / 256;

    for (int L = 0; L < 3; L++) {
        cvt_feat_kernel<<<cvt_blocks, 256>>>(lay_in[L], n);
        for (int r = 0; r < 3; r++) {
            int mat = L * 3 + r;
            gemm_mma_kernel<<<gemm_grid, 256, GEMM_SMEM>>>(
                pAh, pAl, pWh + (size_t)mat * 65536, pWl + (size_t)mat * 65536,
                al[L] + r * 256, ar[L] + r * 256, n);
            int mode = (r == 0) ? 0 : ((L == 2 && r == 2) ? 2 : 1);
            node_agg_kernel<<<agg_blocks, 256>>>(bb[L] + r * 256, lay_out[L],
                                                 (float*)d_out, mode, r * n, n);
        }
    }
}